// round 17
// baseline (speedup 1.0000x reference)
#include <cuda_runtime.h>
#include <cuda_fp16.h>
#include <cstdint>
#include <cstddef>

#define DIM   768
#define HEADS 12
#define HD    64
#define BATCH 16
#define SEQ   3136
#define HWIMG 56
#define M_TOTAL (BATCH * SEQ)   /* 50176 */
#define QKV_N   (3 * DIM)       /* 2304  */
#define BH      (BATCH * HEADS) /* 192 */

// GEMM tiling (mma.sync fp16 m16n8k16): 128x128x64, 256 threads,
// warp tile 64x32, 2 CTAs/SM, 3-stage cp.async pipeline.
#define BM 128
#define BN 128
#define BKH 64                  /* 64 halves = 128B rows */
#define KT (DIM / BKH)          /* 12 */
#define ASZ (BM * BKH * 2)      /* 16KB */
#define BSZ (BN * BKH * 2)      /* 16KB */
#define STAGE (ASZ + BSZ)       /* 32KB */
#define NSTAGE 3
#define SMEM_DYN (NSTAGE * STAGE)   /* 96KB */

#define CSPLIT 7                /* ctx N-split: 3136 = 7 * 448 */
#define CROWS  (SEQ / CSPLIT)   /* 448 */

// ---------------- scratch (static device allocations; no cudaMalloc) -------
__device__ __half g_qh[(size_t)M_TOTAL * DIM];            // q fp16 [M, 768] token-major
__device__ __half g_kT[(size_t)BH * HD * SEQ];            // k fp16 [bh][d][n]
__device__ __half g_vT[(size_t)BH * HD * SEQ];            // v fp16 [bh][e][n]
__device__ float  g_ctxp[(size_t)CSPLIT * BH * HD * HD];  // ctxT partials fp32 [e][d]
__device__ __half g_ctxT[(size_t)BH * HD * HD];           // ctxT fp16 [bh][e][d]
__device__ float  g_attn[(size_t)BATCH * DIM * SEQ];      // attn out [B, C, N] fp32
__device__ __half g_convh[(size_t)BATCH * DIM * SEQ];     // conv out [B, C, N] fp16
__device__ __half g_convT[(size_t)M_TOTAL * DIM];         // conv out [M, C] fp16
__device__ __half g_xh[(size_t)M_TOTAL * DIM];            // x fp16 [M, K]
__device__ __half g_wqT[(size_t)QKV_N * DIM];             // qkv_w^T fp16 [N, K]
__device__ __half g_wpT[(size_t)DIM * DIM];               // proj_w^T fp16 [N, K]

// ---------------------------- PTX helpers ----------------------------------
__device__ __forceinline__ uint32_t cvta_smem(const void* p) {
    uint32_t a;
    asm("{ .reg .u64 t; cvta.to.shared.u64 t, %1; cvt.u32.u64 %0, t; }"
        : "=r"(a) : "l"(p));
    return a;
}

__device__ __forceinline__ void cp16(uint32_t dst, const void* src) {
    asm volatile("cp.async.cg.shared.global [%0], [%1], 16;"
                 :: "r"(dst), "l"(src) : "memory");
}
#define CP_COMMIT() asm volatile("cp.async.commit_group;" ::: "memory")
#define CP_WAIT1()  asm volatile("cp.async.wait_group 1;" ::: "memory")
#define CP_WAIT0()  asm volatile("cp.async.wait_group 0;" ::: "memory")

__device__ __forceinline__ uint32_t lds_u32(uint32_t addr) {
    uint32_t v;
    asm volatile("ld.shared.b32 %0, [%1];" : "=r"(v) : "r"(addr));
    return v;
}

__device__ __forceinline__ void mma_f16(float* c, const uint32_t* a, const uint32_t* b) {
    asm volatile(
        "mma.sync.aligned.m16n8k16.row.col.f32.f16.f16.f32 "
        "{%0,%1,%2,%3}, {%4,%5,%6,%7}, {%8,%9}, {%0,%1,%2,%3};"
        : "+f"(c[0]), "+f"(c[1]), "+f"(c[2]), "+f"(c[3])
        : "r"(a[0]), "r"(a[1]), "r"(a[2]), "r"(a[3]), "r"(b[0]), "r"(b[1]));
}

// ---------------------------------------------------------------------------
// Prepass A: x fp32 -> fp16
// ---------------------------------------------------------------------------
__global__ __launch_bounds__(256) void conv_x_f16(const float* __restrict__ in)
{
    const size_t i = (size_t)blockIdx.x * 256 + threadIdx.x;
    if (i < (size_t)M_TOTAL * DIM / 2) {
        float2 v = ((const float2*)in)[i];
        ((half2*)g_xh)[i] = __float22half2_rn(v);
    }
}

// Prepass B: weight fp32 [K,N] -> fp16 [N,K]
__global__ __launch_bounds__(256) void transpose_w_f16(
    const float* __restrict__ W, __half* __restrict__ out, int N)
{
    const int i = blockIdx.x * 256 + threadIdx.x;
    if (i < (DIM / 2) * N) {
        const int n = i % N, k2 = i / N;
        float a = W[(size_t)(2 * k2) * N + n];
        float b = W[(size_t)(2 * k2 + 1) * N + n];
        *(half2*)&out[(size_t)n * DIM + 2 * k2] = __floats2half2_rn(a, b);
    }
}

// ---------------------------------------------------------------------------
// fp16 GEMM core: C[M,N] = Ah[M,K] @ BhT[N,K]^T   (proven R12/R15 version)
// ---------------------------------------------------------------------------
#define GEMM_BODY(ASRC_EXPR, BSRC_PTR)                                        \
    extern __shared__ char smem[];                                            \
    const uint32_t sb = cvta_smem(smem);                                      \
    const int tid  = threadIdx.x;                                             \
    const int wid  = tid >> 5, lane = tid & 31;                               \
    const int gid  = lane >> 2, tig = lane & 3;                               \
    const int m0 = blockIdx.y * BM, n0 = blockIdx.x * BN;                     \
    const int wm = (wid & 1) * 64, wn = (wid >> 1) * 32;                      \
    auto load_tile = [&](int kt, int buf) {                                   \
        const uint32_t ab = sb + buf * STAGE;                                 \
        const uint32_t bb = ab + ASZ;                                         \
        const int k0 = kt * BKH;                                              \
        _Pragma("unroll")                                                     \
        for (int i = 0; i < 4; i++) {                                         \
            const int c = tid + i * 256;                                      \
            const int m = c >> 3, j = c & 7;                                  \
            cp16(ab + (uint32_t)(m * 128 + ((j ^ (m & 7)) << 4)),             \
                 (ASRC_EXPR) + k0 + j * 8);                                   \
        }                                                                     \
        _Pragma("unroll")                                                     \
        for (int i = 0; i < 4; i++) {                                         \
            const int c = tid + i * 256;                                      \
            const int n = c >> 3, j = c & 7;                                  \
            cp16(bb + (uint32_t)(n * 128 + ((j ^ (n & 7)) << 4)),             \
                 (BSRC_PTR) + (size_t)(n0 + n) * DIM + k0 + j * 8);           \
        }                                                                     \
        CP_COMMIT();                                                          \
    };                                                                        \
    float acc[4][4][4] = {};                                                  \
    load_tile(0, 0);                                                          \
    load_tile(1, 1);                                                          \
    for (int kt = 0; kt < KT; kt++) {                                         \
        if (kt == KT - 1) CP_WAIT0(); else CP_WAIT1();                        \
        __syncthreads();                                                      \
        if (kt + 2 < KT) load_tile(kt + 2, (kt + 2) % NSTAGE);                \
        const uint32_t ab = sb + (kt % NSTAGE) * STAGE;                       \
        const uint32_t bb = ab + ASZ;                                         \
        _Pragma("unroll")                                                     \
        for (int ks = 0; ks < 4; ks++) {                                      \
            const int kp = ks * 8 + tig;                                      \
            uint32_t af[4][4], bf[4][2];                                      \
            _Pragma("unroll")                                                 \
            for (int mt = 0; mt < 4; mt++) {                                  \
                const int m  = wm + mt * 16 + gid;                            \
                const int m8 = m + 8;                                         \
                const uint32_t sw = (uint32_t)(gid << 2);                     \
                af[mt][0] = lds_u32(ab + ((uint32_t)(m  * 32) + ((uint32_t)kp ^ sw)) * 4);       \
                af[mt][1] = lds_u32(ab + ((uint32_t)(m8 * 32) + ((uint32_t)kp ^ sw)) * 4);       \
                af[mt][2] = lds_u32(ab + ((uint32_t)(m  * 32) + ((uint32_t)(kp + 4) ^ sw)) * 4); \
                af[mt][3] = lds_u32(ab + ((uint32_t)(m8 * 32) + ((uint32_t)(kp + 4) ^ sw)) * 4); \
            }                                                                 \
            _Pragma("unroll")                                                 \
            for (int nt = 0; nt < 4; nt++) {                                  \
                const int n = wn + nt * 8 + gid;                              \
                const uint32_t sw = (uint32_t)(gid << 2);                     \
                bf[nt][0] = lds_u32(bb + ((uint32_t)(n * 32) + ((uint32_t)kp ^ sw)) * 4);        \
                bf[nt][1] = lds_u32(bb + ((uint32_t)(n * 32) + ((uint32_t)(kp + 4) ^ sw)) * 4);  \
            }                                                                 \
            _Pragma("unroll")                                                 \
            for (int mt = 0; mt < 4; mt++)                                    \
                _Pragma("unroll")                                             \
                for (int nt = 0; nt < 4; nt++)                                \
                    mma_f16(acc[mt][nt], af[mt], bf[nt]);                     \
        }                                                                     \
    }

// ---------------------------------------------------------------------------
// Kernel 1: QKV GEMM + bias + activation.
// q -> g_qh fp16 [M,768] token-major; k,v -> g_kT/g_vT fp16 [bh][ch][n].
// ---------------------------------------------------------------------------
__global__ __launch_bounds__(256, 2) void gemm_qkv_tc(
    const float* __restrict__ bias)
{
    GEMM_BODY(g_xh + (size_t)(m0 + m) * DIM, g_wqT)

    const int region = n0 / DIM;   // 0=q, 1=k, 2=v  (128 | 768)
    const float qsc = 0.125f;
#pragma unroll
    for (int mt = 0; mt < 4; mt++) {
        const int ma = m0 + wm + mt * 16 + gid;
        const int mb = ma + 8;
#pragma unroll
        for (int nt = 0; nt < 4; nt++) {
            const int cidx = n0 + wn + nt * 8 + 2 * tig;
            const float b0 = bias[cidx], b1 = bias[cidx + 1];
            float v0 = acc[mt][nt][0] + b0, v1 = acc[mt][nt][1] + b1;
            float v2 = acc[mt][nt][2] + b0, v3 = acc[mt][nt][3] + b1;
            if (region == 0) {
                v0 = fmaxf(v0, 0.f) * qsc; v1 = fmaxf(v1, 0.f) * qsc;
                v2 = fmaxf(v2, 0.f) * qsc; v3 = fmaxf(v3, 0.f) * qsc;
                *(half2*)&g_qh[(size_t)ma * DIM + cidx] = __floats2half2_rn(v0, v1);
                *(half2*)&g_qh[(size_t)mb * DIM + cidx] = __floats2half2_rn(v2, v3);
            } else {
                __half* dst = (region == 1) ? g_kT : g_vT;
                if (region == 1) {
                    v0 = fmaxf(v0, 0.f); v1 = fmaxf(v1, 0.f);
                    v2 = fmaxf(v2, 0.f); v3 = fmaxf(v3, 0.f);
                }
                const int c = cidx - region * DIM;   // 0..767
                const int h = c >> 6, d = c & 63;
                const int ba = ma / SEQ, na = ma - ba * SEQ;
                const int bb2 = mb / SEQ, nb = mb - bb2 * SEQ;
                const size_t basea = ((size_t)(ba * HEADS + h) * HD + d) * SEQ;
                const size_t baseb = ((size_t)(bb2 * HEADS + h) * HD + d) * SEQ;
                dst[basea + na]       = __float2half_rn(v0);
                dst[basea + SEQ + na] = __float2half_rn(v1);   // d+1 row
                dst[baseb + nb]       = __float2half_rn(v2);
                dst[baseb + SEQ + nb] = __float2half_rn(v3);
            }
        }
    }
}

// ---------------------------------------------------------------------------
// Kernel 5: projection GEMM.  out[M,768] = convT @ wpT^T + b  (fp32 out)
// ---------------------------------------------------------------------------
__global__ __launch_bounds__(256, 2) void gemm_proj_tc(
    const float* __restrict__ bias, float* __restrict__ out)
{
    GEMM_BODY(g_convT + (size_t)(m0 + m) * DIM, g_wpT)

#pragma unroll
    for (int mt = 0; mt < 4; mt++) {
        const int r0 = m0 + wm + mt * 16 + gid;
#pragma unroll
        for (int nt = 0; nt < 4; nt++) {
            const int cidx = n0 + wn + nt * 8 + 2 * tig;
            const float b0 = bias[cidx], b1 = bias[cidx + 1];
            *(float2*)(out + (size_t)r0 * DIM + cidx) =
                make_float2(acc[mt][nt][0] + b0, acc[mt][nt][1] + b1);
            *(float2*)(out + (size_t)(r0 + 8) * DIM + cidx) =
                make_float2(acc[mt][nt][2] + b0, acc[mt][nt][3] + b1);
        }
    }
}

// ---------------------------------------------------------------------------
// Kernel 2a: ctxT[e][d] partial = sum_n vT[e][n] * kT[d][n]  (tensor cores)
// grid (192 bh, 7 sp), 256 threads; 8 warps = 4 e-tiles(16) x 2 d-tiles(32).
// smem tiles [64 rows][8 u32], u32 swizzle j ^ (r&7)  (conflict-free).
// ---------------------------------------------------------------------------
__global__ __launch_bounds__(256) void ctx_part_kernel()
{
    const int bh = blockIdx.x;
    const int sp = blockIdx.y;

    __shared__ uint32_t sv[64 * 8];
    __shared__ uint32_t sk[64 * 8];

    const int tid = threadIdx.x;
    const int wid = tid >> 5, lane = tid & 31;
    const int gid = lane >> 2, tig = lane & 3;
    const int we = (wid & 3) * 16;
    const int wd = (wid >> 2) * 32;

    const __half* vbase = g_vT + (size_t)bh * HD * SEQ;
    const __half* kbase = g_kT + (size_t)bh * HD * SEQ;

    float acc[4][4] = {};

    for (int step = 0; step < CROWS / 16; step++) {
        const int n0 = sp * CROWS + step * 16;
        __syncthreads();
#pragma unroll
        for (int t = 0; t < 2; t++) {
            const int idx = tid + t * 256;          // 0..511
            const int r = idx >> 3, j = idx & 7;
            const int sj = j ^ (r & 7);
            sv[r * 8 + sj] = *(const uint32_t*)(vbase + (size_t)r * SEQ + n0 + j * 2);
            sk[r * 8 + sj] = *(const uint32_t*)(kbase + (size_t)r * SEQ + n0 + j * 2);
        }
        __syncthreads();

        uint32_t a[4], b[4][2];
        const int ra = we + gid, rb = ra + 8;
        a[0] = sv[ra * 8 + (tig ^ (ra & 7))];
        a[1] = sv[rb * 8 + (tig ^ (rb & 7))];
        a[2] = sv[ra * 8 + ((tig + 4) ^ (ra & 7))];
        a[3] = sv[rb * 8 + ((tig + 4) ^ (rb & 7))];
#pragma unroll
        for (int nt = 0; nt < 4; nt++) {
            const int d = wd + nt * 8 + gid;
            b[nt][0] = sk[d * 8 + (tig ^ (d & 7))];
            b[nt][1] = sk[d * 8 + ((tig + 4) ^ (d & 7))];
        }
#pragma unroll
        for (int nt = 0; nt < 4; nt++)
            mma_f16(acc[nt], a, b[nt]);
    }

    float* cb = g_ctxp + ((size_t)sp * BH + bh) * HD * HD;
    const int er = we + gid;
#pragma unroll
    for (int nt = 0; nt < 4; nt++) {
        const int dc = wd + nt * 8 + 2 * tig;
        cb[er * HD + dc]           = acc[nt][0];
        cb[er * HD + dc + 1]       = acc[nt][1];
        cb[(er + 8) * HD + dc]     = acc[nt][2];
        cb[(er + 8) * HD + dc + 1] = acc[nt][3];
    }
}

// Kernel 2b: reduce 7 partials -> g_ctxT fp16.  192 blocks x 256 threads.
__global__ __launch_bounds__(256) void ctx_reduce_kernel()
{
    const int bh = blockIdx.x;
    const int tid = threadIdx.x;
    const size_t off = (size_t)bh * HD * HD;
#pragma unroll
    for (int s = 0; s < 8; s++) {
        const int e2 = (tid + s * 256) * 2;         // pair index over 4096
        float2 a = *(const float2*)(g_ctxp + off + e2);
#pragma unroll
        for (int p = 1; p < CSPLIT; p++) {
            const float2 b = *(const float2*)(g_ctxp + (size_t)p * BH * HD * HD + off + e2);
            a.x += b.x; a.y += b.y;
        }
        *(half2*)&g_ctxT[off + e2] = __floats2half2_rn(a.x, a.y);
    }
}

// ---------------------------------------------------------------------------
// Kernel 3: apply = q @ ctx via tensor cores.
// out[n][e] = sum_d q[n][d] * ctxT[e][d].  grid (49 n-tiles of 64, 192 bh).
// A smem: q [64 tok][64 halves], B smem: ctxT [64 e][64 halves], GEMM swizzle.
// 8 warps = 4 m-tiles(16) x 2 e-tiles(32). Writes g_attn fp32 channel-major.
// ---------------------------------------------------------------------------
__global__ __launch_bounds__(256) void apply_kernel()
{
    const int n0 = blockIdx.x * 64;
    const int bh = blockIdx.y;
    const int b = bh / HEADS, h = bh % HEADS;

    __shared__ uint32_t sA[64 * 32];
    __shared__ uint32_t sB[64 * 32];

    const int tid = threadIdx.x;
    const int wid = tid >> 5, lane = tid & 31;
    const int gid = lane >> 2, tig = lane & 3;
    const int wm = (wid & 3) * 16;
    const int we = (wid >> 2) * 32;

    const uint32_t* qsrc = (const uint32_t*)(g_qh + ((size_t)(b * SEQ + n0)) * DIM + h * HD);
    const uint32_t* csrc = (const uint32_t*)(g_ctxT + (size_t)bh * HD * HD);

#pragma unroll
    for (int t = 0; t < 8; t++) {
        const int idx = tid + t * 256;              // 0..2047
        const int r = idx >> 5, kp = idx & 31;
        const int skp = kp ^ ((r & 7) << 2);
        sA[r * 32 + skp] = qsrc[(size_t)r * (DIM / 2) + kp];
        sB[r * 32 + skp] = csrc[r * 32 + kp];
    }
    __syncthreads();

    float acc[4][4] = {};
#pragma unroll
    for (int ks = 0; ks < 4; ks++) {
        const int kp = ks * 8 + tig;
        uint32_t a[4], bfr[4][2];
        const int ma = wm + gid, mb = ma + 8;
        const uint32_t swa = (uint32_t)((ma & 7) << 2);
        const uint32_t swb = (uint32_t)((mb & 7) << 2);
        a[0] = sA[ma * 32 + ((uint32_t)kp ^ swa)];
        a[1] = sA[mb * 32 + ((uint32_t)kp ^ swb)];
        a[2] = sA[ma * 32 + ((uint32_t)(kp + 4) ^ swa)];
        a[3] = sA[mb * 32 + ((uint32_t)(kp + 4) ^ swb)];
#pragma unroll
        for (int nt = 0; nt < 4; nt++) {
            const int e = we + nt * 8 + gid;
            const uint32_t swe = (uint32_t)((e & 7) << 2);
            bfr[nt][0] = sB[e * 32 + ((uint32_t)kp ^ swe)];
            bfr[nt][1] = sB[e * 32 + ((uint32_t)(kp + 4) ^ swe)];
        }
#pragma unroll
        for (int nt = 0; nt < 4; nt++)
            mma_f16(acc[nt], a, bfr[nt]);
    }

    const int mr = wm + gid;
#pragma unroll
    for (int nt = 0; nt < 4; nt++) {
        const int e = we + nt * 8 + 2 * tig;
        float* o0 = g_attn + ((size_t)(bh * HD + e)) * SEQ + n0;
        float* o1 = o0 + SEQ;                       // e+1
        o0[mr]     = acc[nt][0];
        o1[mr]     = acc[nt][1];
        o0[mr + 8] = acc[nt][2];
        o1[mr + 8] = acc[nt][3];
    }
}

// ---------------------------------------------------------------------------
// Kernel 4: depthwise 3x3 conv (fp32 in g_attn, fp16 out [B,C,N])
// ---------------------------------------------------------------------------
__global__ __launch_bounds__(256) void dwconv_kernel(
    const float* __restrict__ w, const float* __restrict__ bias)
{
    const int bc = blockIdx.x;
    const int c = bc % DIM;

    __shared__ float sm[58 * 58];

    const int tid = threadIdx.x;
    for (int i = tid; i < 58 * 58; i += 256) sm[i] = 0.f;
    __syncthreads();

    const float* ib = g_attn + (size_t)bc * SEQ;
    for (int i = tid; i < SEQ; i += 256) {
        const int y = i / HWIMG, x = i - y * HWIMG;
        sm[(y + 1) * 58 + x + 1] = ib[i];
    }
    __syncthreads();

    const float* wc = w + c * 9;
    const float w0 = wc[0], w1 = wc[1], w2 = wc[2];
    const float w3 = wc[3], w4 = wc[4], w5 = wc[5];
    const float w6 = wc[6], w7 = wc[7], w8 = wc[8];
    const float bb = bias[c];

    __half* ob = g_convh + (size_t)bc * SEQ;
    for (int q = tid; q < 784; q += 256) {
        const int y = q / 14;
        const int xq = (q - y * 14) * 4;
        const float* p0 = &sm[y * 58 + xq];
        const float* p1 = p0 + 58;
        const float* p2 = p0 + 116;
        float r0[6], r1[6], r2[6];
#pragma unroll
        for (int t = 0; t < 6; t++) { r0[t] = p0[t]; r1[t] = p1[t]; r2[t] = p2[t]; }
        float4 o;
        o.x = bb; o.y = bb; o.z = bb; o.w = bb;
        o.x = fmaf(w0, r0[0], o.x); o.x = fmaf(w1, r0[1], o.x); o.x = fmaf(w2, r0[2], o.x);
        o.x = fmaf(w3, r1[0], o.x); o.x = fmaf(w4, r1[1], o.x); o.x = fmaf(w5, r1[2], o.x);
        o.x = fmaf(w6, r2[0], o.x); o.x = fmaf(w7, r2[1], o.x); o.x = fmaf(w8, r2[2], o.x);
        o.y = fmaf(w0, r0[1], o.y); o.y = fmaf(w1, r0[2], o.y); o.y = fmaf(w2, r0[3], o.y);
        o.y = fmaf(w3, r1[1], o.y); o.y = fmaf(w4, r1[2], o.y); o.y = fmaf(w5, r1[3], o.y);
        o.y = fmaf(w6, r2[1], o.y); o.y = fmaf(w7, r2[2], o.y); o.y = fmaf(w8, r2[3], o.y);
        o.z = fmaf(w0, r0[2], o.z); o.z = fmaf(w1, r0[3], o.z); o.z = fmaf(w2, r0[4], o.z);
        o.z = fmaf(w3, r1[2], o.z); o.z = fmaf(w4, r1[3], o.z); o.z = fmaf(w5, r1[4], o.z);
        o.z = fmaf(w6, r2[2], o.z); o.z = fmaf(w7, r2[3], o.z); o.z = fmaf(w8, r2[4], o.z);
        o.w = fmaf(w0, r0[3], o.w); o.w = fmaf(w1, r0[4], o.w); o.w = fmaf(w2, r0[5], o.w);
        o.w = fmaf(w3, r1[3], o.w); o.w = fmaf(w4, r1[4], o.w); o.w = fmaf(w5, r1[5], o.w);
        o.w = fmaf(w6, r2[3], o.w); o.w = fmaf(w7, r2[4], o.w); o.w = fmaf(w8, r2[5], o.w);
        half2* op = (half2*)(ob + y * HWIMG + xq);
        op[0] = __floats2half2_rn(o.x, o.y);
        op[1] = __floats2half2_rn(o.z, o.w);
    }
}

// ---------------------------------------------------------------------------
// Kernel 4b: transpose conv fp16 [B,C,N] -> [M,C]  (64x64 tiles)
// ---------------------------------------------------------------------------
__global__ __launch_bounds__(256) void conv_transpose_kernel()
{
    __shared__ __half sm[64 * 66];
    const int nt = blockIdx.x;
    const int ct = blockIdx.y;
    const int b  = blockIdx.z;
    const int tid = threadIdx.x;

#pragma unroll
    for (int i = 0; i < 8; i++) {
        const int li = i * 256 + tid;
        const int c = li >> 5, n2 = li & 31;
        half2 v = *(const half2*)&g_convh[((size_t)(b * DIM + ct * 64 + c)) * SEQ + nt * 64 + 2 * n2];
        *(half2*)&sm[c * 66 + 2 * n2] = v;
    }
    __syncthreads();
#pragma unroll
    for (int i = 0; i < 8; i++) {
        const int li = i * 256 + tid;
        const int n = li >> 5, c2 = li & 31;
        half2 v = __halves2half2(sm[(2 * c2) * 66 + n], sm[(2 * c2 + 1) * 66 + n]);
        *(half2*)&g_convT[((size_t)(b * SEQ + nt * 64 + n)) * DIM + ct * 64 + 2 * c2] = v;
    }
}

// ---------------------------------------------------------------------------
extern "C" void kernel_launch(void* const* d_in, const int* in_sizes, int n_in,
                              void* d_out, int out_size)
{
    (void)in_sizes; (void)n_in; (void)out_size;
    const float* x      = (const float*)d_in[0];
    const float* qkv_w  = (const float*)d_in[1];
    const float* qkv_b  = (const float*)d_in[2];
    const float* dw_w   = (const float*)d_in[3];
    const float* dw_b   = (const float*)d_in[4];
    const float* proj_w = (const float*)d_in[5];
    const float* proj_b = (const float*)d_in[6];
    float* out = (float*)d_out;

    cudaFuncSetAttribute(gemm_qkv_tc, cudaFuncAttributeMaxDynamicSharedMemorySize, SMEM_DYN);
    cudaFuncSetAttribute(gemm_proj_tc, cudaFuncAttributeMaxDynamicSharedMemorySize, SMEM_DYN);

    __half* wq_p;  cudaGetSymbolAddress((void**)&wq_p, g_wqT);
    __half* wp_p;  cudaGetSymbolAddress((void**)&wp_p, g_wpT);

    const int nxh = (int)((size_t)M_TOTAL * DIM / 2);
    conv_x_f16<<<(nxh + 255) / 256, 256>>>(x);
    transpose_w_f16<<<((DIM / 2) * QKV_N + 255) / 256, 256>>>(qkv_w, wq_p, QKV_N);
    transpose_w_f16<<<((DIM / 2) * DIM + 255) / 256, 256>>>(proj_w, wp_p, DIM);

    gemm_qkv_tc<<<dim3(QKV_N / BN, M_TOTAL / BM), 256, SMEM_DYN>>>(qkv_b);
    ctx_part_kernel<<<dim3(BH, CSPLIT), 256>>>();
    ctx_reduce_kernel<<<BH, 256>>>();
    apply_kernel<<<dim3(SEQ / 64, BH), 256>>>();
    dwconv_kernel<<<BATCH * DIM, 256>>>(dw_w, dw_b);
    conv_transpose_kernel<<<dim3(SEQ / 64, DIM / 64, BATCH), 256>>>();
    gemm_proj_tc<<<dim3(DIM / BN, M_TOTAL / BM), 256, SMEM_DYN>>>(proj_b, out);
}